// round 5
// baseline (speedup 1.0000x reference)
#include <cuda_runtime.h>

// Matcher: IoU of origin-centered anchor boxes [N,2] vs gt boxes [B,M,4],
// plus argmax over anchors.
//   ious[b,n,m] = inter / (area_a + area_b - inter)
//   inter       = min(aw, gw) * min(ah, gh)      (exact: boxes share center)
//   matches[b,m] = argmax_n ious[b,n,m]          (first max on ties)
//
// Output buffer layout (tuple flatten order): [B*M] matches (as float),
// then [B*N*M] ious.

#define NANCH 1024
#define BATCH 128
#define MGT   256

__global__ __launch_bounds__(256, 4)
void matcher_kernel(const float* __restrict__ anchors,   // [N,2]
                    const float* __restrict__ gt,        // [B,M,4]
                    float* __restrict__ out)             // [B*M + B*N*M]
{
    __shared__ float4 s_anchor[NANCH];        // {aw, ah, aw*ah, 0}
    __shared__ float  s_val[64 * 17];         // padded: stride-17 kills bank conflicts
    __shared__ int    s_idx[64 * 17];

    const int tx  = threadIdx.x;              // 0..15 : m-quad within block
    const int ty  = threadIdx.y;              // 0..15 : anchor strip (n ascending)
    const int tid = ty * 16 + tx;
    const int b   = blockIdx.x;               // 0..127
    const int mq  = blockIdx.y;               // 0..3  : 64 m per block
    const int m0  = mq * 64 + tx * 4;         // first of the 4 m this thread owns

    // ---- preload anchors into smem, precompute area ----
    const float2* a2 = (const float2*)anchors;
    for (int n = tid; n < NANCH; n += 256) {
        float2 a = a2[n];
        s_anchor[n] = make_float4(a.x, a.y, __fmul_rn(a.x, a.y), 0.0f);
    }
    __syncthreads();

    // ---- per-thread gt constants (4 consecutive m) ----
    float gw[4], gh[4], areab[4];
    const float4* g4 = (const float4*)(gt + ((size_t)b * MGT + m0) * 4);
#pragma unroll
    for (int j = 0; j < 4; j++) {
        float4 g = g4[j];                       // xmin, ymin, xmax, ymax
        gw[j]    = __fsub_rn(g.z, g.x);
        gh[j]    = __fsub_rn(g.w, g.y);
        areab[j] = __fmul_rn(gw[j], gh[j]);
    }

    float best[4] = { -1e30f, -1e30f, -1e30f, -1e30f };
    int   bidx[4] = { 0, 0, 0, 0 };

    float* iou_out = out + BATCH * MGT;         // ious start after matches
    const size_t base = (size_t)b * NANCH * MGT + m0;
    const int n0 = ty * 64;

    // ---- main loop: 64 anchors, 4 m each → one STG.128 per iter ----
#pragma unroll 4
    for (int i = 0; i < 64; i++) {
        const int n = n0 + i;
        float4 a = s_anchor[n];
        float v[4];
#pragma unroll
        for (int j = 0; j < 4; j++) {
            float iw    = fminf(a.x, gw[j]);
            float ih    = fminf(a.y, gh[j]);
            float inter = __fmul_rn(iw, ih);
            // reference order: (area_a + area_b) - inter, no FMA contraction
            float uni   = __fsub_rn(__fadd_rn(a.z, areab[j]), inter);
            v[j] = __fdiv_rn(inter, uni);       // IEEE: bit-exact vs reference
            if (v[j] > best[j]) { best[j] = v[j]; bidx[j] = n; }
        }
        float4 r = make_float4(v[0], v[1], v[2], v[3]);
        *(float4*)(iou_out + base + (size_t)n * MGT) = r;
    }

    // ---- argmax reduction across the 16 anchor strips (ty ascending = n ascending) ----
#pragma unroll
    for (int j = 0; j < 4; j++) {
        s_val[(tx * 4 + j) * 17 + ty] = best[j];
        s_idx[(tx * 4 + j) * 17 + ty] = bidx[j];
    }
    __syncthreads();

    if (tid < 64) {
        float bv = s_val[tid * 17];
        int   bi = s_idx[tid * 17];
#pragma unroll
        for (int k = 1; k < 16; k++) {
            float v = s_val[tid * 17 + k];
            int   ix = s_idx[tid * 17 + k];
            if (v > bv) { bv = v; bi = ix; }    // strict > keeps lowest n on ties
        }
        out[(size_t)b * MGT + mq * 64 + tid] = (float)bi;
    }
}

extern "C" void kernel_launch(void* const* d_in, const int* in_sizes, int n_in,
                              void* d_out, int out_size)
{
    const float* anchors = (const float*)d_in[0];   // [1024, 2]
    const float* gt      = (const float*)d_in[1];   // [128, 256, 4]
    float* out           = (float*)d_out;

    dim3 block(16, 16);
    dim3 grid(BATCH, MGT / 64);                     // 128 x 4 = 512 blocks
    matcher_kernel<<<grid, block>>>(anchors, gt, out);
}

// round 6
// speedup vs baseline: 1.1941x; 1.1941x over previous
#include <cuda_runtime.h>

// Matcher: IoU of origin-centered anchor boxes [N,2] vs gt boxes [B,M,4],
// plus argmax over anchors.
//   iw = min(aw, gw), ih = min(ah, gh)   (bit-exact: boxes share center,
//                                         /2 and *2 are exact in fp32)
//   iou = inter / ((area_a + area_b) - inter), all __f*_rn -> bit-identical
//   matches[b,m] = argmax_n iou (first max on ties)
// Output: [B*M] matches (as float), then [B*N*M] ious.

#define NANCH     1024
#define BATCH     128
#define MGT       256
#define M_PER_CTA 32
#define STRIPS    32
#define STRIP_N   (NANCH / STRIPS)   // 32 anchors per thread

__global__ __launch_bounds__(256, 5)
void matcher_kernel(const float* __restrict__ anchors,   // [N,2]
                    const float* __restrict__ gt,        // [B,M,4]
                    float* __restrict__ out)             // [B*M + B*N*M]
{
    __shared__ float4 s_anchor[NANCH];          // {aw, ah, aw*ah, 0}
    __shared__ float  s_val[M_PER_CTA * 33];    // stride 33: conflict-free
    __shared__ int    s_idx[M_PER_CTA * 33];

    const int t  = threadIdx.x;
    const int tx = t & 7;                       // m-quad within CTA (0..7)
    const int s  = t >> 3;                      // anchor strip (0..31)
    const int b  = blockIdx.x;                  // batch
    const int m0 = blockIdx.y * M_PER_CTA + tx * 4;
    const int n0 = s * STRIP_N;

    // ---- anchors -> smem with precomputed area (4 per thread) ----
    const float2* a2 = (const float2*)anchors;
#pragma unroll
    for (int k = 0; k < 4; k++) {
        int n = t + k * 256;
        float2 a = a2[n];
        s_anchor[n] = make_float4(a.x, a.y, __fmul_rn(a.x, a.y), 0.0f);
    }
    __syncthreads();

    // ---- per-thread gt constants (4 consecutive m) ----
    float gw[4], gh[4], areab[4];
    const float4* g4 = (const float4*)(gt + ((size_t)b * MGT + m0) * 4);
#pragma unroll
    for (int j = 0; j < 4; j++) {
        float4 g = g4[j];                       // xmin, ymin, xmax, ymax
        gw[j]    = __fsub_rn(g.z, g.x);
        gh[j]    = __fsub_rn(g.w, g.y);
        areab[j] = __fmul_rn(gw[j], gh[j]);
    }

    float best[4] = { -1e30f, -1e30f, -1e30f, -1e30f };
    int   bidx[4] = { 0, 0, 0, 0 };

    // iou output pointer for (b, n0, m0); advances one n-row per iter
    float* p = out + BATCH * MGT
                   + (size_t)b * NANCH * MGT + (size_t)n0 * MGT + m0;

    // ---- main loop: 32 anchors x 4 m -> one STG.128 per iter ----
#pragma unroll 8
    for (int i = 0; i < STRIP_N; i++) {
        float4 a = s_anchor[n0 + i];
        float v[4];
#pragma unroll
        for (int j = 0; j < 4; j++) {
            float iw    = fminf(a.x, gw[j]);
            float ih    = fminf(a.y, gh[j]);
            float inter = __fmul_rn(iw, ih);
            float uni   = __fsub_rn(__fadd_rn(a.z, areab[j]), inter);
            v[j] = __fdiv_rn(inter, uni);       // IEEE: bit-exact vs reference
            if (v[j] > best[j]) { best[j] = v[j]; bidx[j] = n0 + i; }
        }
        __stcs((float4*)p, make_float4(v[0], v[1], v[2], v[3]));
        p += MGT;
    }

    // ---- argmax reduction across 32 strips (ascending = n order) ----
#pragma unroll
    for (int j = 0; j < 4; j++) {
        int ml = tx * 4 + j;                    // local m (0..31)
        s_val[ml * 33 + s] = best[j];
        s_idx[ml * 33 + s] = bidx[j];
    }
    __syncthreads();

    if (t < M_PER_CTA) {
        const float* vv = s_val + t * 33;
        const int*   ii = s_idx + t * 33;
        float bv = vv[0];
        int   bi = ii[0];
#pragma unroll
        for (int k = 1; k < STRIPS; k++) {
            float v = vv[k];
            int   x = ii[k];
            if (v > bv) { bv = v; bi = x; }     // strict > keeps lowest n
        }
        out[(size_t)b * MGT + blockIdx.y * M_PER_CTA + t] = (float)bi;
    }
}

extern "C" void kernel_launch(void* const* d_in, const int* in_sizes, int n_in,
                              void* d_out, int out_size)
{
    const float* anchors = (const float*)d_in[0];   // [1024, 2]
    const float* gt      = (const float*)d_in[1];   // [128, 256, 4]
    float* out           = (float*)d_out;

    dim3 block(256);
    dim3 grid(BATCH, MGT / M_PER_CTA);              // 128 x 8 = 1024 CTAs
    matcher_kernel<<<grid, block>>>(anchors, gt, out);
}